// round 9
// baseline (speedup 1.0000x reference)
#include <cuda_runtime.h>
#include <cuda_fp16.h>
#include <cstdint>
#include <cstddef>

// B=32, T=64 -> BT=2048. audio [BT,128], video [BT,48,512], W_audio[512,128],
// b_audio[512], W_video[512,512], b_video[512], W_v[48,512], W_g[48,512], W_h[1,48]
#define BT_TOTAL 2048
#define SVH 520               // vs row stride (halfs); 1040B -> LDSM conflict-free
#define KT 64                 // A k-tile (8 tiles over K=512)
#define STH 72                // fp16 tile row stride (halfs); 144B -> LDSM conflict-free

// ---------------- device scratch ----------------
__device__ uint2 g_Wvf[64 * 32 * 32];   // W_video fp16 B-frags: [h8][k16][lane] (512KB)
__device__ uint2 g_Wvvf[6 * 32 * 32];   // W_v     fp16 B-frags: [m8][k16][lane] (48KB)
__device__ float g_WaT[128 * 512];      // W_audio transposed [k][h] (256KB)
__device__ float g_inter[BT_TOTAL * 48];

// ---------------- helpers ----------------
__device__ __forceinline__ uint32_t packh2(float lo, float hi) {
    __half2 h = __floats2half2_rn(lo, hi);
    return *(uint32_t*)&h;
}

__device__ __forceinline__ void mma_f16(float& d0, float& d1, float& d2, float& d3,
                                        uint32_t a0, uint32_t a1, uint32_t a2, uint32_t a3,
                                        uint32_t b0, uint32_t b1) {
    asm volatile(
        "mma.sync.aligned.m16n8k16.row.col.f32.f16.f16.f32 "
        "{%0,%1,%2,%3}, {%4,%5,%6,%7}, {%8,%9}, {%0,%1,%2,%3};\n"
        : "+f"(d0), "+f"(d1), "+f"(d2), "+f"(d3)
        : "r"(a0), "r"(a1), "r"(a2), "r"(a3), "r"(b0), "r"(b1));
}

__device__ __forceinline__ void ldsm_x4(uint32_t& a0, uint32_t& a1, uint32_t& a2, uint32_t& a3,
                                        uint32_t saddr) {
    asm volatile("ldmatrix.sync.aligned.m8n8.x4.shared.b16 {%0,%1,%2,%3}, [%4];"
                 : "=r"(a0), "=r"(a1), "=r"(a2), "=r"(a3) : "r"(saddr));
}

__device__ __forceinline__ void cp_async16(uint32_t saddr, const float* gaddr) {
    asm volatile("cp.async.ca.shared.global [%0], [%1], 16;" :: "r"(saddr), "l"(gaddr));
}
#define CP_COMMIT() asm volatile("cp.async.commit_group;")
#define CP_WAIT(n)  asm volatile("cp.async.wait_group %0;" :: "n"(n))

__device__ __forceinline__ void prefetch_l1(const void* p) {
    asm volatile("prefetch.global.L1 [%0];" :: "l"(p));
}

// ---------------- kernel 1: fp16 frag-ordered weights + W_audio transpose ----
__global__ void prep_kernel(const float* __restrict__ Wvid, const float* __restrict__ Wv,
                            const float* __restrict__ Wa) {
    int idx = blockIdx.x * 256 + threadIdx.x;
    if (idx < 64 * 32 * 32) {
        int lane = idx & 31, tile = idx >> 5;
        int h8 = tile >> 5, ks = tile & 31;
        int row = h8 * 8 + (lane >> 2);
        int col = ks * 16 + (lane & 3) * 2;
        const float* W = Wvid + (size_t)row * 512 + col;
        g_Wvf[idx] = make_uint2(packh2(W[0], W[1]), packh2(W[8], W[9]));
    } else if (idx < 64 * 32 * 32 + 6 * 32 * 32) {
        int j = idx - 64 * 32 * 32;
        int lane = j & 31, tile = j >> 5;
        int m8 = tile >> 5, ks = tile & 31;
        int row = m8 * 8 + (lane >> 2);
        int col = ks * 16 + (lane & 3) * 2;
        const float* W = Wv + (size_t)row * 512 + col;
        g_Wvvf[j] = make_uint2(packh2(W[0], W[1]), packh2(W[8], W[9]));
    } else {
        int j2 = idx - (64 * 32 * 32 + 6 * 32 * 32);
        if (j2 < 128 * 512) {
            int k = j2 >> 9, h = j2 & 511;
            g_WaT[j2] = Wa[(size_t)h * 128 + k];   // coalesced write, strided read
        }
    }
}

// ---------------- kernel 2: audio path -> inter[bt][48] ----------------
// Thread t owns h = t and t+256. Weights read from transposed g_WaT (coalesced).
__global__ __launch_bounds__(256) void audio_kernel(const float* __restrict__ audio,
                                                    const float* __restrict__ b_audio,
                                                    const float* __restrict__ W_g) {
    __shared__ float audio_s[16 * 128];
    __shared__ float a_s[16 * 512];
    int t = threadIdx.x;
    int cb = blockIdx.x;

    const float* ag = audio + (size_t)cb * 16 * 128;
#pragma unroll
    for (int i = 0; i < 8; i++) audio_s[t + i * 256] = ag[t + i * 256];
    __syncthreads();

    float acc0[16], acc1[16];
#pragma unroll
    for (int r = 0; r < 16; r++) { acc0[r] = 0.f; acc1[r] = 0.f; }

#pragma unroll 2
    for (int kb = 0; kb < 16; kb++) {          // 8 k per block
        float w0[8], w1[8];
#pragma unroll
        for (int q = 0; q < 8; q++) {
            w0[q] = g_WaT[(size_t)(kb * 8 + q) * 512 + t];
            w1[q] = g_WaT[(size_t)(kb * 8 + q) * 512 + t + 256];
        }
#pragma unroll
        for (int r = 0; r < 16; r++) {
            const float4* ap = (const float4*)(audio_s + r * 128 + kb * 8);
            float4 a0 = ap[0], a1 = ap[1];
            acc0[r] += w0[0] * a0.x + w0[1] * a0.y + w0[2] * a0.z + w0[3] * a0.w
                     + w0[4] * a1.x + w0[5] * a1.y + w0[6] * a1.z + w0[7] * a1.w;
            acc1[r] += w1[0] * a0.x + w1[1] * a0.y + w1[2] * a0.z + w1[3] * a0.w
                     + w1[4] * a1.x + w1[5] * a1.y + w1[6] * a1.z + w1[7] * a1.w;
        }
    }
    float b0 = b_audio[t], b1 = b_audio[t + 256];
#pragma unroll
    for (int r = 0; r < 16; r++) {
        float s0 = acc0[r] + b0, s1 = acc1[r] + b1;
        a_s[r * 512 + t]       = s0 > 0.f ? s0 : 0.f;
        a_s[r * 512 + t + 256] = s1 > 0.f ? s1 : 0.f;
    }
    __syncthreads();

    // inter[r][m] = a[r] . W_g[m]   (W_g is 98KB -> L1-resident)
#pragma unroll
    for (int j = 0; j < 3; j++) {
        int idx = t + j * 256;
        int r = idx / 48, m = idx % 48;
        const float4* ar = (const float4*)(a_s + r * 512);
        const float4* wg = (const float4*)(W_g + (size_t)m * 512);
        float s = 0.f;
#pragma unroll 8
        for (int kk = 0; kk < 128; kk++) {
            float4 a4 = ar[kk], w4 = wg[kk];
            s += a4.x * w4.x + a4.y * w4.y + a4.z * w4.z + a4.w * w4.w;
        }
        g_inter[(size_t)cb * 768 + idx] = s;
    }
}

// ---------------- probe: keeps ncu capture window on main_kernel ------
__global__ void probe_kernel() {}

// ---------------- kernel 3: fused main, 2 bt per CTA, 512 threads ----------------
#define OF_F32   99840
#define OF_H16   148992
#define OF_BVS   176640
#define OF_INTER 178688
#define OF_WH    179072
#define OF_ZP    179264
#define OF_RED   180032
#define OF_AL    180048
#define SMEM_BYTES 180448

__device__ __forceinline__ void issue_tile(uint32_t fbase, const float* gsrc, int t) {
    // 96 rows x 64 floats = 1536 16B chunks; gmem row stride 512 floats
#pragma unroll
    for (int i = 0; i < 3; i++) {
        int g = t + i * 512;
        int row = g >> 4, c4 = g & 15;
        cp_async16(fbase + (uint32_t)g * 16u, gsrc + (size_t)row * 512 + c4 * 4);
    }
}

// convert f32 stage s -> h16 stage s. Thread t converts EXACTLY the chunks it
// cp.async'd in issue_tile -> cp.async.wait_group alone orders this.
__device__ __forceinline__ void convert_tile(char* smc, int s, int t) {
    const float4* f4 = (const float4*)(smc + OF_F32 + s * 24576);
    __half* h16 = (__half*)(smc + OF_H16 + s * 13824);
#pragma unroll
    for (int i = 0; i < 3; i++) {
        int g = t + i * 512;
        int row = g >> 4, c4 = g & 15;
        float4 v = f4[g];
        *(uint2*)&h16[row * STH + c4 * 4] = make_uint2(packh2(v.x, v.y), packh2(v.z, v.w));
    }
}

__global__ __launch_bounds__(512, 1) void main_kernel(const float* __restrict__ video,
                                                      const float* __restrict__ b_video,
                                                      const float* __restrict__ W_h,
                                                      float* __restrict__ out) {
    extern __shared__ char smc[];
    uint32_t sbase = (uint32_t)__cvta_generic_to_shared(smc);
    __half* vs     = (__half*)smc;
    float* bvs     = (float*)(smc + OF_BVS);
    float* inter_s = (float*)(smc + OF_INTER);
    float* wh_s    = (float*)(smc + OF_WH);
    float* zpart   = (float*)(smc + OF_ZP);
    float* red     = (float*)(smc + OF_RED);
    float* alpha_s = (float*)(smc + OF_AL);

    int t = threadIdx.x;
    int blk = blockIdx.x;                 // bt = 2*blk, 2*blk+1
    int lane = t & 31, w = t >> 5;        // 16 warps
    int qid = lane >> 2, tq = lane & 3;

    const float* Vg = video + (size_t)blk * 96 * 512;

    // ---- phase 0: pipeline prologue ----
    issue_tile(sbase + OF_F32, Vg, t);                  CP_COMMIT();   // t0
    issue_tile(sbase + OF_F32 + 24576, Vg + KT, t);     CP_COMMIT();   // t1
    bvs[t] = b_video[t];
    if (t < 96) inter_s[t] = g_inter[(size_t)blk * 96 + t];
    if (t < 48) wh_s[t] = W_h[t];

    float acc[6][4][4];
#pragma unroll
    for (int mt = 0; mt < 6; mt++)
#pragma unroll
        for (int j = 0; j < 4; j++)
#pragma unroll
            for (int r = 0; r < 4; r++) acc[mt][j][r] = 0.f;

    const uint2* Bp = g_Wvf + (size_t)(w * 4) * 32 * 32 + lane;
    // warm L1 for k16 step 0's B frags
#pragma unroll
    for (int j = 0; j < 4; j++) prefetch_l1(Bp + (size_t)(j * 32) * 32);

    uint32_t lds_a = sbase + OF_H16 + (uint32_t)(((lane & 15) * STH + (lane >> 4) * 8) * 2);

    CP_WAIT(1);                    // t0 landed (own chunks)
    convert_tile(smc, 0, t);       // h16[0] <- t0
    __syncthreads();               // h16[0] + bvs/inter visible to all

    // ---- phase 1: v = relu(V @ W_video^T + b)  (M=96, N=512, K=512) ----
    for (int tile = 0; tile < 8; ++tile) {
        int s = tile & 1;
        if (tile + 2 < 8) {        // f32[s] freed by convert(tile) last iter
            issue_tile(sbase + OF_F32 + s * 24576, Vg + (size_t)(tile + 2) * KT, t);
            CP_COMMIT();
        }
        if (tile + 1 < 8) {
            if (tile + 2 < 8) { CP_WAIT(1); } else { CP_WAIT(0); }
            convert_tile(smc, s ^ 1, t);   // h16[s^1] <- tile+1 (own chunks only)
        }

        uint32_t abase = lds_a + (uint32_t)(s * 13824);
#pragma unroll
        for (int kk = 0; kk < 4; kk++) {
            int kg = tile * 4 + kk;        // k16 step 0..31
            // single-buffered B frags (L1-hit thanks to last step's prefetch)
            uint2 bb[4];
#pragma unroll
            for (int j = 0; j < 4; j++) {
                bb[j] = Bp[(size_t)(j * 32 + kg) * 32];
                prefetch_l1(Bp + (size_t)(j * 32 + kg + 1) * 32);  // next k16
            }
#pragma unroll
            for (int mt = 0; mt < 6; mt++) {
                uint32_t a0, a1, a2, a3;
                ldsm_x4(a0, a1, a2, a3, abase + (uint32_t)((mt * 16 * STH + kk * 16) * 2));
#pragma unroll
                for (int j = 0; j < 4; j++)
                    mma_f16(acc[mt][j][0], acc[mt][j][1], acc[mt][j][2], acc[mt][j][3],
                            a0, a1, a2, a3, bb[j].x, bb[j].y);
            }
        }
        __syncthreads();   // mma(tile) reads done; h16[s^1] visible for next iter
    }

    // epilogue: relu(+bias), pack fp16 pairs, store v to smem
#pragma unroll
    for (int mt = 0; mt < 6; mt++) {
#pragma unroll
        for (int j = 0; j < 4; j++) {
            int r0 = mt * 16 + qid;
            int h0 = w * 32 + j * 8 + tq * 2;
            float bv0 = bvs[h0], bv1 = bvs[h0 + 1];
            float x0 = acc[mt][j][0] + bv0; x0 = x0 > 0.f ? x0 : 0.f;
            float x1 = acc[mt][j][1] + bv1; x1 = x1 > 0.f ? x1 : 0.f;
            float x2 = acc[mt][j][2] + bv0; x2 = x2 > 0.f ? x2 : 0.f;
            float x3 = acc[mt][j][3] + bv1; x3 = x3 > 0.f ? x3 : 0.f;
            *(uint32_t*)&vs[r0 * SVH + h0]       = packh2(x0, x1);
            *(uint32_t*)&vs[(r0 + 8) * SVH + h0] = packh2(x2, x3);
        }
    }
    __syncthreads();

    // ---- phase 2: content = v @ W_v^T (+inter), tanh, z partials ----
    if (w < 12) {
        int btl = w / 6, wl = w % 6;
        int mt = wl >> 1, nh = wl & 1;
        float cacc[3][4];
#pragma unroll
        for (int j = 0; j < 3; j++)
#pragma unroll
            for (int r = 0; r < 4; r++) cacc[j][r] = 0.f;

        const uint2* Bp2 = g_Wvvf + (size_t)(nh * 3) * 32 * 32 + lane;
        uint2 bb2[2][3];
#pragma unroll
        for (int j = 0; j < 3; j++) bb2[0][j] = Bp2[(size_t)(j * 32) * 32];

        uint32_t abase2 = sbase +
            (uint32_t)((((btl * 48 + mt * 16 + (lane & 15)) * SVH) + (lane >> 4) * 8) * 2);
#pragma unroll 4
        for (int ks = 0; ks < 32; ks++) {
            int cur = ks & 1;
            if (ks < 31) {
#pragma unroll
                for (int j = 0; j < 3; j++)
                    bb2[cur ^ 1][j] = Bp2[(size_t)(j * 32 + ks + 1) * 32];
            }
            uint32_t a0, a1, a2, a3;
            ldsm_x4(a0, a1, a2, a3, abase2 + (uint32_t)(ks * 32));
#pragma unroll
            for (int j = 0; j < 3; j++)
                mma_f16(cacc[j][0], cacc[j][1], cacc[j][2], cacc[j][3],
                        a0, a1, a2, a3, bb2[cur][j].x, bb2[cur][j].y);
        }

        int n0 = mt * 16 + qid, n1 = n0 + 8;
        float i0 = inter_s[btl * 48 + n0], i1 = inter_s[btl * 48 + n1];
        float p0 = 0.f, p1 = 0.f;
#pragma unroll
        for (int j = 0; j < 3; j++) {
            int m0i = (nh * 3 + j) * 8 + tq * 2;
            float wh0 = wh_s[m0i], wh1 = wh_s[m0i + 1];
            p0 += tanhf(cacc[j][0] + i0) * wh0 + tanhf(cacc[j][1] + i0) * wh1;
            p1 += tanhf(cacc[j][2] + i1) * wh0 + tanhf(cacc[j][3] + i1) * wh1;
        }
        p0 += __shfl_xor_sync(0xffffffffu, p0, 1);
        p0 += __shfl_xor_sync(0xffffffffu, p0, 2);
        p1 += __shfl_xor_sync(0xffffffffu, p1, 1);
        p1 += __shfl_xor_sync(0xffffffffu, p1, 2);
        if (tq == 0) {
            zpart[btl * 96 + n0 * 2 + nh] = p0;
            zpart[btl * 96 + n1 * 2 + nh] = p1;
        }
    }
    __syncthreads();

    // ---- phase 3: softmax over 48, per bt ----
    if (t < 96) {
        int btl = t / 48, n = t % 48;
        alpha_s[t] = zpart[btl * 96 + n * 2] + zpart[btl * 96 + n * 2 + 1];
    }
    __syncthreads();
    if (t == 0 || t == 256) {
        int btl = t >> 8;
        float m = -1e30f;
        for (int n = 0; n < 48; n++) m = fmaxf(m, alpha_s[btl * 48 + n]);
        red[btl * 2] = m;
    }
    __syncthreads();
    if (t < 96) alpha_s[t] = expf(alpha_s[t] - red[(t / 48) * 2]);
    __syncthreads();
    if (t == 0 || t == 256) {
        int btl = t >> 8;
        float s = 0.f;
        for (int n = 0; n < 48; n++) s += alpha_s[btl * 48 + n];
        red[btl * 2 + 1] = 1.0f / s;
    }
    __syncthreads();

    // ---- phase 4: c[k] = sum_n alpha[n] * V[n][k], exact V from global ----
    {
        int btl = t >> 8, k = t & 255;
        const float* Vrow = Vg + (size_t)btl * 48 * 512;
        float inv = red[btl * 2 + 1];
        const float* al = alpha_s + btl * 48;
        float s0 = 0.f, s1 = 0.f;
#pragma unroll 8
        for (int n = 0; n < 48; n++) {
            float a = al[n];
            s0 += a * Vrow[(size_t)n * 512 + k];
            s1 += a * Vrow[(size_t)n * 512 + k + 256];
        }
        float* ob = out + (size_t)(blk * 2 + btl) * 512;
        ob[k] = s0 * inv;
        ob[k + 256] = s1 * inv;
    }
}

// ---------------- launch ----------------
extern "C" void kernel_launch(void* const* d_in, const int* in_sizes, int n_in,
                              void* d_out, int out_size) {
    const float* audio   = (const float*)d_in[0];
    const float* video   = (const float*)d_in[1];
    const float* W_audio = (const float*)d_in[2];
    const float* b_audio = (const float*)d_in[3];
    const float* W_video = (const float*)d_in[4];
    const float* b_video = (const float*)d_in[5];
    const float* W_v     = (const float*)d_in[6];
    const float* W_g     = (const float*)d_in[7];
    const float* W_h     = (const float*)d_in[8];
    float* out = (float*)d_out;

    (void)in_sizes; (void)n_in; (void)out_size;

    cudaFuncSetAttribute(main_kernel, cudaFuncAttributeMaxDynamicSharedMemorySize, SMEM_BYTES);

    prep_kernel<<<536, 256>>>(W_video, W_v, W_audio);
    audio_kernel<<<BT_TOTAL / 16, 256>>>(audio, b_audio, W_g);
    probe_kernel<<<1, 32>>>();   // keeps ncu -s5 capture window on main_kernel
    main_kernel<<<BT_TOTAL / 2, 512, SMEM_BYTES>>>(video, b_video, W_h, out);
}

// round 11
// speedup vs baseline: 1.1327x; 1.1327x over previous
#include <cuda_runtime.h>
#include <cuda_fp16.h>
#include <cstdint>
#include <cstddef>

// B=32, T=64 -> BT=2048. audio [BT,128], video [BT,48,512], W_audio[512,128],
// b_audio[512], W_video[512,512], b_video[512], W_v[48,512], W_g[48,512], W_h[1,48]
#define BT_TOTAL 2048
#define SVH 520     // vs row stride (halfs); LDSM conflict-free (proven R6-R8)
#define KT  32      // A k-tile (16 tiles over K=512)
#define STH 40      // h16 tile row stride (halfs) = 80B; LDSM bank-distinct

// ---------------- device scratch ----------------
__device__ uint2 g_Wvf[64 * 32 * 32];   // W_video fp16 B-frags: [h8][k16][lane] (512KB)
__device__ uint2 g_Wvvf[6 * 32 * 32];   // W_v     fp16 B-frags: [m8][k16][lane] (48KB)
__device__ float g_WaT[128 * 512];      // W_audio transposed [k][h] (256KB)
__device__ float g_inter[BT_TOTAL * 48];

// ---------------- helpers ----------------
__device__ __forceinline__ uint32_t packh2(float lo, float hi) {
    __half2 h = __floats2half2_rn(lo, hi);
    return *(uint32_t*)&h;
}

__device__ __forceinline__ void mma_f16(float& d0, float& d1, float& d2, float& d3,
                                        uint32_t a0, uint32_t a1, uint32_t a2, uint32_t a3,
                                        uint32_t b0, uint32_t b1) {
    asm volatile(
        "mma.sync.aligned.m16n8k16.row.col.f32.f16.f16.f32 "
        "{%0,%1,%2,%3}, {%4,%5,%6,%7}, {%8,%9}, {%0,%1,%2,%3};\n"
        : "+f"(d0), "+f"(d1), "+f"(d2), "+f"(d3)
        : "r"(a0), "r"(a1), "r"(a2), "r"(a3), "r"(b0), "r"(b1));
}

__device__ __forceinline__ void ldsm_x4(uint32_t& a0, uint32_t& a1, uint32_t& a2, uint32_t& a3,
                                        uint32_t saddr) {
    asm volatile("ldmatrix.sync.aligned.m8n8.x4.shared.b16 {%0,%1,%2,%3}, [%4];"
                 : "=r"(a0), "=r"(a1), "=r"(a2), "=r"(a3) : "r"(saddr));
}

__device__ __forceinline__ void cp_async16(uint32_t saddr, const float* gaddr) {
    asm volatile("cp.async.ca.shared.global [%0], [%1], 16;" :: "r"(saddr), "l"(gaddr));
}
#define CP_COMMIT() asm volatile("cp.async.commit_group;")
#define CP_WAIT(n)  asm volatile("cp.async.wait_group %0;" :: "n"(n))

// ---------------- kernel 1: fp16 frag-ordered weights + W_audio transpose ----
__global__ void prep_kernel(const float* __restrict__ Wvid, const float* __restrict__ Wv,
                            const float* __restrict__ Wa) {
    int idx = blockIdx.x * 256 + threadIdx.x;
    if (idx < 64 * 32 * 32) {
        int lane = idx & 31, tile = idx >> 5;
        int h8 = tile >> 5, ks = tile & 31;
        int row = h8 * 8 + (lane >> 2);
        int col = ks * 16 + (lane & 3) * 2;
        const float* W = Wvid + (size_t)row * 512 + col;
        g_Wvf[idx] = make_uint2(packh2(W[0], W[1]), packh2(W[8], W[9]));
    } else if (idx < 64 * 32 * 32 + 6 * 32 * 32) {
        int j = idx - 64 * 32 * 32;
        int lane = j & 31, tile = j >> 5;
        int m8 = tile >> 5, ks = tile & 31;
        int row = m8 * 8 + (lane >> 2);
        int col = ks * 16 + (lane & 3) * 2;
        const float* W = Wv + (size_t)row * 512 + col;
        g_Wvvf[j] = make_uint2(packh2(W[0], W[1]), packh2(W[8], W[9]));
    } else {
        int j2 = idx - (64 * 32 * 32 + 6 * 32 * 32);
        if (j2 < 128 * 512) {
            int k = j2 >> 9, h = j2 & 511;
            g_WaT[j2] = Wa[(size_t)h * 128 + k];
        }
    }
}

// ---------------- kernel 2: audio path -> inter[bt][48] ----------------
__global__ __launch_bounds__(256) void audio_kernel(const float* __restrict__ audio,
                                                    const float* __restrict__ b_audio,
                                                    const float* __restrict__ W_g) {
    __shared__ float audio_s[16 * 128];
    __shared__ float a_s[16 * 512];
    int t = threadIdx.x;
    int cb = blockIdx.x;

    const float* ag = audio + (size_t)cb * 16 * 128;
#pragma unroll
    for (int i = 0; i < 8; i++) audio_s[t + i * 256] = ag[t + i * 256];
    __syncthreads();

    float acc0[16], acc1[16];
#pragma unroll
    for (int r = 0; r < 16; r++) { acc0[r] = 0.f; acc1[r] = 0.f; }

#pragma unroll 2
    for (int kb = 0; kb < 16; kb++) {
        float w0[8], w1[8];
#pragma unroll
        for (int q = 0; q < 8; q++) {
            w0[q] = g_WaT[(size_t)(kb * 8 + q) * 512 + t];
            w1[q] = g_WaT[(size_t)(kb * 8 + q) * 512 + t + 256];
        }
#pragma unroll
        for (int r = 0; r < 16; r++) {
            const float4* ap = (const float4*)(audio_s + r * 128 + kb * 8);
            float4 a0 = ap[0], a1 = ap[1];
            acc0[r] += w0[0] * a0.x + w0[1] * a0.y + w0[2] * a0.z + w0[3] * a0.w
                     + w0[4] * a1.x + w0[5] * a1.y + w0[6] * a1.z + w0[7] * a1.w;
            acc1[r] += w1[0] * a0.x + w1[1] * a0.y + w1[2] * a0.z + w1[3] * a0.w
                     + w1[4] * a1.x + w1[5] * a1.y + w1[6] * a1.z + w1[7] * a1.w;
        }
    }
    float b0 = b_audio[t], b1 = b_audio[t + 256];
#pragma unroll
    for (int r = 0; r < 16; r++) {
        float s0 = acc0[r] + b0, s1 = acc1[r] + b1;
        a_s[r * 512 + t]       = s0 > 0.f ? s0 : 0.f;
        a_s[r * 512 + t + 256] = s1 > 0.f ? s1 : 0.f;
    }
    __syncthreads();

#pragma unroll
    for (int j = 0; j < 3; j++) {
        int idx = t + j * 256;
        int r = idx / 48, m = idx % 48;
        const float4* ar = (const float4*)(a_s + r * 512);
        const float4* wg = (const float4*)(W_g + (size_t)m * 512);
        float s = 0.f;
#pragma unroll 8
        for (int kk = 0; kk < 128; kk++) {
            float4 a4 = ar[kk], w4 = wg[kk];
            s += a4.x * w4.x + a4.y * w4.y + a4.z * w4.z + a4.w * w4.w;
        }
        g_inter[(size_t)cb * 768 + idx] = s;
    }
}

// ---------------- probe: keeps ncu capture window on main_kernel ------
__global__ void probe_kernel() {}

// ---------------- kernel 3: fused main, 1 bt per CTA, 256 threads, occ 2 ------
// smem (72960 B/CTA; 2 CTAs/SM = 145920 <= 228KB):
//   vs (half, 48 x 520)             @0       49920
//   f32 A stages (2 x 48 x 32 f32)  @49920   12288
//   h16 A stages (2 x 48 x 40 h)    @62208    7680
//   bvs (512 f32)                   @69888    2048
//   inter(48) @71936 | wh(48) @72128 | zpart(96) @72320
//   red(2) @72704 | alpha(48) @72712 -> end 72904
#define OF_F32   49920
#define OF_H16   62208
#define OF_BVS   69888
#define OF_INTER 71936
#define OF_WH    72128
#define OF_ZP    72320
#define OF_RED   72704
#define OF_AL    72712
#define SMEM_BYTES 72960
#define F32_STG  6144    // bytes per f32 stage (48*32*4)
#define H16_STG  3840    // bytes per h16 stage (48*40*2)

__device__ __forceinline__ void issue_tile(uint32_t fbase, const float* gsrc, int t) {
    // 48 rows x 32 floats = 384 16B chunks
    for (int g = t; g < 384; g += 256) {
        int row = g >> 3, c4 = g & 7;
        cp_async16(fbase + (uint32_t)g * 16u, gsrc + (size_t)row * 512 + c4 * 4);
    }
}

// Thread t converts exactly the chunks it cp.async'd -> wait_group orders it.
__device__ __forceinline__ void convert_tile(char* smc, int s, int t) {
    const float4* f4 = (const float4*)(smc + OF_F32 + s * F32_STG);
    __half* h16 = (__half*)(smc + OF_H16 + s * H16_STG);
    for (int g = t; g < 384; g += 256) {
        int row = g >> 3, c4 = g & 7;
        float4 v = f4[g];
        *(uint2*)&h16[row * STH + c4 * 4] = make_uint2(packh2(v.x, v.y), packh2(v.z, v.w));
    }
}

__global__ __launch_bounds__(256, 2) void main_kernel(const float* __restrict__ video,
                                                      const float* __restrict__ b_video,
                                                      const float* __restrict__ W_h,
                                                      float* __restrict__ out) {
    extern __shared__ char smc[];
    uint32_t sbase = (uint32_t)__cvta_generic_to_shared(smc);
    __half* vs     = (__half*)smc;
    float* bvs     = (float*)(smc + OF_BVS);
    float* inter_s = (float*)(smc + OF_INTER);
    float* wh_s    = (float*)(smc + OF_WH);
    float* zpart   = (float*)(smc + OF_ZP);
    float* red     = (float*)(smc + OF_RED);
    float* alpha_s = (float*)(smc + OF_AL);

    int t = threadIdx.x;
    int bt = blockIdx.x;
    int lane = t & 31, w = t >> 5;        // 8 warps
    int qid = lane >> 2, tq = lane & 3;

    const float* Vg = video + (size_t)bt * 48 * 512;

    // ---- phase 0: pipeline prologue ----
    issue_tile(sbase + OF_F32, Vg, t);                  CP_COMMIT();   // t0
    issue_tile(sbase + OF_F32 + F32_STG, Vg + KT, t);   CP_COMMIT();   // t1
    bvs[t] = b_video[t];
    bvs[t + 256] = b_video[t + 256];
    if (t < 48) { inter_s[t] = g_inter[(size_t)bt * 48 + t]; wh_s[t] = W_h[t]; }

    // warp w owns h in [w*64, w*64+64): 8 n8 tiles (2 halves of 4); 3 m16 tiles
    float acc[3][8][4];
#pragma unroll
    for (int mt = 0; mt < 3; mt++)
#pragma unroll
        for (int j = 0; j < 8; j++)
#pragma unroll
            for (int r = 0; r < 4; r++) acc[mt][j][r] = 0.f;

    const uint2* Bp = g_Wvf + (size_t)(w * 8) * 32 * 32 + lane;
    // bb[hf][j] = B frag for n8 tile (hf*4+j) of the CURRENT k16 step
    uint2 bb[2][4];
#pragma unroll
    for (int hf = 0; hf < 2; hf++)
#pragma unroll
        for (int j = 0; j < 4; j++)
            bb[hf][j] = Bp[(size_t)((hf * 4 + j) * 32) * 32];

    uint32_t lds_a = sbase + OF_H16 + (uint32_t)(((lane & 15) * STH + (lane >> 4) * 8) * 2);

    CP_WAIT(1);                    // t0 landed (own chunks)
    convert_tile(smc, 0, t);       // h16[0] <- t0
    __syncthreads();

    // ---- phase 1: v = relu(V @ W_video^T + b)  (M=48, N=512, K=512) ----
    for (int tile = 0; tile < 16; ++tile) {
        int s = tile & 1;
        if (tile + 2 < 16) {
            issue_tile(sbase + OF_F32 + s * F32_STG, Vg + (size_t)(tile + 2) * KT, t);
            CP_COMMIT();
        }
        if (tile + 1 < 16) {
            if (tile + 2 < 16) { CP_WAIT(1); } else { CP_WAIT(0); }
            convert_tile(smc, s ^ 1, t);
        }

        uint32_t abase = lds_a + (uint32_t)(s * H16_STG);
#pragma unroll
        for (int kk = 0; kk < 2; kk++) {
            int kg = tile * 2 + kk;        // k16 step 0..31
            uint32_t a[3][4];
#pragma unroll
            for (int mt = 0; mt < 3; mt++)
                ldsm_x4(a[mt][0], a[mt][1], a[mt][2], a[mt][3],
                        abase + (uint32_t)((mt * 16 * STH + kk * 16) * 2));

            // low half (tiles 0-3), then refill bb[0] for kg+1
#pragma unroll
            for (int mt = 0; mt < 3; mt++)
#pragma unroll
                for (int j = 0; j < 4; j++)
                    mma_f16(acc[mt][j][0], acc[mt][j][1], acc[mt][j][2], acc[mt][j][3],
                            a[mt][0], a[mt][1], a[mt][2], a[mt][3], bb[0][j].x, bb[0][j].y);
            if (kg < 31) {
#pragma unroll
                for (int j = 0; j < 4; j++)
                    bb[0][j] = Bp[(size_t)(j * 32 + kg + 1) * 32];
            }
            // high half (tiles 4-7), then refill bb[1] for kg+1
#pragma unroll
            for (int mt = 0; mt < 3; mt++)
#pragma unroll
                for (int j = 0; j < 4; j++)
                    mma_f16(acc[mt][4 + j][0], acc[mt][4 + j][1], acc[mt][4 + j][2], acc[mt][4 + j][3],
                            a[mt][0], a[mt][1], a[mt][2], a[mt][3], bb[1][j].x, bb[1][j].y);
            if (kg < 31) {
#pragma unroll
                for (int j = 0; j < 4; j++)
                    bb[1][j] = Bp[(size_t)((4 + j) * 32 + kg + 1) * 32];
            }
        }
        __syncthreads();
    }

    // epilogue: relu(+bias), pack fp16 pairs, store v to smem (full 512 cols!)
#pragma unroll
    for (int mt = 0; mt < 3; mt++) {
#pragma unroll
        for (int jj = 0; jj < 8; jj++) {
            int r0 = mt * 16 + qid;
            int h0 = w * 64 + jj * 8 + tq * 2;
            float bv0 = bvs[h0], bv1 = bvs[h0 + 1];
            float x0 = acc[mt][jj][0] + bv0; x0 = x0 > 0.f ? x0 : 0.f;
            float x1 = acc[mt][jj][1] + bv1; x1 = x1 > 0.f ? x1 : 0.f;
            float x2 = acc[mt][jj][2] + bv0; x2 = x2 > 0.f ? x2 : 0.f;
            float x3 = acc[mt][jj][3] + bv1; x3 = x3 > 0.f ? x3 : 0.f;
            *(uint32_t*)&vs[r0 * SVH + h0]       = packh2(x0, x1);
            *(uint32_t*)&vs[(r0 + 8) * SVH + h0] = packh2(x2, x3);
        }
    }
    __syncthreads();

    // ---- phase 2: content = v @ W_v^T (+inter), tanh, z partials ----
    // 6 warps; warp owns m16 tile x 3 n8 tiles exclusively
    if (w < 6) {
        int mt = w >> 1, nh = w & 1;
        float cacc[3][4];
#pragma unroll
        for (int j = 0; j < 3; j++)
#pragma unroll
            for (int r = 0; r < 4; r++) cacc[j][r] = 0.f;

        const uint2* Bp2 = g_Wvvf + (size_t)(nh * 3) * 32 * 32 + lane;
        uint2 bb2[2][3];
#pragma unroll
        for (int j = 0; j < 3; j++) bb2[0][j] = Bp2[(size_t)(j * 32) * 32];

        uint32_t abase2 = sbase +
            (uint32_t)((((mt * 16 + (lane & 15)) * SVH) + (lane >> 4) * 8) * 2);
#pragma unroll 4
        for (int ks = 0; ks < 32; ks++) {
            int cur = ks & 1;
            if (ks < 31) {
#pragma unroll
                for (int j = 0; j < 3; j++)
                    bb2[cur ^ 1][j] = Bp2[(size_t)(j * 32 + ks + 1) * 32];
            }
            uint32_t a0, a1, a2, a3;
            ldsm_x4(a0, a1, a2, a3, abase2 + (uint32_t)(ks * 32));
#pragma unroll
            for (int j = 0; j < 3; j++)
                mma_f16(cacc[j][0], cacc[j][1], cacc[j][2], cacc[j][3],
                        a0, a1, a2, a3, bb2[cur][j].x, bb2[cur][j].y);
        }

        int n0 = mt * 16 + qid, n1 = n0 + 8;
        float i0 = inter_s[n0], i1 = inter_s[n1];
        float p0 = 0.f, p1 = 0.f;
#pragma unroll
        for (int j = 0; j < 3; j++) {
            int m0i = (nh * 3 + j) * 8 + tq * 2;
            float wh0 = wh_s[m0i], wh1 = wh_s[m0i + 1];
            p0 += tanhf(cacc[j][0] + i0) * wh0 + tanhf(cacc[j][1] + i0) * wh1;
            p1 += tanhf(cacc[j][2] + i1) * wh0 + tanhf(cacc[j][3] + i1) * wh1;
        }
        p0 += __shfl_xor_sync(0xffffffffu, p0, 1);
        p0 += __shfl_xor_sync(0xffffffffu, p0, 2);
        p1 += __shfl_xor_sync(0xffffffffu, p1, 1);
        p1 += __shfl_xor_sync(0xffffffffu, p1, 2);
        if (tq == 0) {
            zpart[n0 * 2 + nh] = p0;
            zpart[n1 * 2 + nh] = p1;
        }
    }
    __syncthreads();

    // ---- phase 3: softmax over 48 ----
    if (t < 48) alpha_s[t] = zpart[t * 2] + zpart[t * 2 + 1];
    __syncthreads();
    if (t == 0) {
        float m = -1e30f;
        for (int n = 0; n < 48; n++) m = fmaxf(m, alpha_s[n]);
        red[0] = m;
    }
    __syncthreads();
    if (t < 48) alpha_s[t] = expf(alpha_s[t] - red[0]);
    __syncthreads();
    if (t == 0) {
        float s = 0.f;
        for (int n = 0; n < 48; n++) s += alpha_s[n];
        red[1] = 1.0f / s;
    }
    __syncthreads();

    // ---- phase 4: c[k] = sum_n alpha[n] * V[n][k], exact V from global ----
    {
        float inv = red[1];
        float s0 = 0.f, s1 = 0.f;
#pragma unroll 8
        for (int n = 0; n < 48; n++) {
            float a = alpha_s[n];
            s0 += a * Vg[(size_t)n * 512 + t];
            s1 += a * Vg[(size_t)n * 512 + t + 256];
        }
        float* ob = out + (size_t)bt * 512;
        ob[t] = s0 * inv;
        ob[t + 256] = s1 * inv;
    }
}

// ---------------- launch ----------------
extern "C" void kernel_launch(void* const* d_in, const int* in_sizes, int n_in,
                              void* d_out, int out_size) {
    const float* audio   = (const float*)d_in[0];
    const float* video   = (const float*)d_in[1];
    const float* W_audio = (const float*)d_in[2];
    const float* b_audio = (const float*)d_in[3];
    const float* W_video = (const float*)d_in[4];
    const float* b_video = (const float*)d_in[5];
    const float* W_v     = (const float*)d_in[6];
    const float* W_g     = (const float*)d_in[7];
    const float* W_h     = (const float*)d_in[8];
    float* out = (float*)d_out;

    (void)in_sizes; (void)n_in; (void)out_size;

    cudaFuncSetAttribute(main_kernel, cudaFuncAttributeMaxDynamicSharedMemorySize, SMEM_BYTES);

    prep_kernel<<<536, 256>>>(W_video, W_v, W_audio);
    audio_kernel<<<BT_TOTAL / 16, 256>>>(audio, b_audio, W_g);
    probe_kernel<<<1, 32>>>();   // keeps ncu -s5 capture window on main_kernel
    main_kernel<<<BT_TOTAL, 256, SMEM_BYTES>>>(video, b_video, W_h, out);
}

// round 13
// speedup vs baseline: 1.4635x; 1.2920x over previous
#include <cuda_runtime.h>
#include <cuda_fp16.h>
#include <cstdint>
#include <cstddef>

// B=32, T=64 -> BT=2048. audio [BT,128], video [BT,48,512], W_audio[512,128],
// b_audio[512], W_video[512,512], b_video[512], W_v[48,512], W_g[48,512], W_h[1,48]
#define BT_TOTAL 2048
#define SVH 520     // A/vs row stride (halfs); 1040B = 65x16B -> LDSM conflict-free

// ---------------- device scratch ----------------
__device__ uint2 g_Wvf[64 * 32 * 32];   // W_video fp16 B-frags: [h8][k16][lane] (512KB)
__device__ uint2 g_Wvvf[6 * 32 * 32];   // W_v     fp16 B-frags: [m8][k16][lane] (48KB)
__device__ float g_WaT[128 * 512];      // W_audio transposed [k][h] (256KB)
__device__ float g_inter[BT_TOTAL * 48];

// ---------------- helpers ----------------
__device__ __forceinline__ uint32_t packh2(float lo, float hi) {
    __half2 h = __floats2half2_rn(lo, hi);
    return *(uint32_t*)&h;
}

__device__ __forceinline__ void mma_f16(float& d0, float& d1, float& d2, float& d3,
                                        uint32_t a0, uint32_t a1, uint32_t a2, uint32_t a3,
                                        uint32_t b0, uint32_t b1) {
    asm volatile(
        "mma.sync.aligned.m16n8k16.row.col.f32.f16.f16.f32 "
        "{%0,%1,%2,%3}, {%4,%5,%6,%7}, {%8,%9}, {%0,%1,%2,%3};\n"
        : "+f"(d0), "+f"(d1), "+f"(d2), "+f"(d3)
        : "r"(a0), "r"(a1), "r"(a2), "r"(a3), "r"(b0), "r"(b1));
}

__device__ __forceinline__ void ldsm_x4(uint32_t& a0, uint32_t& a1, uint32_t& a2, uint32_t& a3,
                                        uint32_t saddr) {
    asm volatile("ldmatrix.sync.aligned.m8n8.x4.shared.b16 {%0,%1,%2,%3}, [%4];"
                 : "=r"(a0), "=r"(a1), "=r"(a2), "=r"(a3) : "r"(saddr));
}

// ---------------- kernel 1: fp16 frag-ordered weights + W_audio transpose ----
__global__ void prep_kernel(const float* __restrict__ Wvid, const float* __restrict__ Wv,
                            const float* __restrict__ Wa) {
    int idx = blockIdx.x * 256 + threadIdx.x;
    if (idx < 64 * 32 * 32) {
        int lane = idx & 31, tile = idx >> 5;
        int h8 = tile >> 5, ks = tile & 31;
        int row = h8 * 8 + (lane >> 2);
        int col = ks * 16 + (lane & 3) * 2;
        const float* W = Wvid + (size_t)row * 512 + col;
        g_Wvf[idx] = make_uint2(packh2(W[0], W[1]), packh2(W[8], W[9]));
    } else if (idx < 64 * 32 * 32 + 6 * 32 * 32) {
        int j = idx - 64 * 32 * 32;
        int lane = j & 31, tile = j >> 5;
        int m8 = tile >> 5, ks = tile & 31;
        int row = m8 * 8 + (lane >> 2);
        int col = ks * 16 + (lane & 3) * 2;
        const float* W = Wv + (size_t)row * 512 + col;
        g_Wvvf[j] = make_uint2(packh2(W[0], W[1]), packh2(W[8], W[9]));
    } else {
        int j2 = idx - (64 * 32 * 32 + 6 * 32 * 32);
        if (j2 < 128 * 512) {
            int k = j2 >> 9, h = j2 & 511;
            g_WaT[j2] = Wa[(size_t)h * 128 + k];
        }
    }
}

// ---------------- kernel 2: audio path -> inter, 8 bt per CTA, 256 CTAs -----
__global__ __launch_bounds__(256) void audio_kernel(const float* __restrict__ audio,
                                                    const float* __restrict__ b_audio,
                                                    const float* __restrict__ W_g) {
    __shared__ float audio_s[8 * 128];   // 4KB
    __shared__ float a_s[8 * 512];       // 16KB
    __shared__ float wchunk[48 * 65];    // 12.2KB, padded stride 65
    int t = threadIdx.x;
    int cb = blockIdx.x;                 // 8 bt rows

    const float* ag = audio + (size_t)cb * 8 * 128;
#pragma unroll
    for (int i = 0; i < 4; i++) audio_s[t + i * 256] = ag[t + i * 256];
    __syncthreads();

    // phase A: a[r][h] = relu(sum_k audio[r][k] * WaT[k][h] + b[h]); h = t, t+256
    float acc0[8], acc1[8];
#pragma unroll
    for (int r = 0; r < 8; r++) { acc0[r] = 0.f; acc1[r] = 0.f; }
#pragma unroll 2
    for (int kb = 0; kb < 16; kb++) {
        float w0[8], w1[8];
#pragma unroll
        for (int q = 0; q < 8; q++) {
            w0[q] = g_WaT[(size_t)(kb * 8 + q) * 512 + t];
            w1[q] = g_WaT[(size_t)(kb * 8 + q) * 512 + t + 256];
        }
#pragma unroll
        for (int r = 0; r < 8; r++) {
            const float4* ap = (const float4*)(audio_s + r * 128 + kb * 8);
            float4 a0 = ap[0], a1 = ap[1];
            acc0[r] += w0[0] * a0.x + w0[1] * a0.y + w0[2] * a0.z + w0[3] * a0.w
                     + w0[4] * a1.x + w0[5] * a1.y + w0[6] * a1.z + w0[7] * a1.w;
            acc1[r] += w1[0] * a0.x + w1[1] * a0.y + w1[2] * a0.z + w1[3] * a0.w
                     + w1[4] * a1.x + w1[5] * a1.y + w1[6] * a1.z + w1[7] * a1.w;
        }
    }
    float b0 = b_audio[t], b1 = b_audio[t + 256];
#pragma unroll
    for (int r = 0; r < 8; r++) {
        float s0 = acc0[r] + b0, s1 = acc1[r] + b1;
        a_s[r * 512 + t]       = s0 > 0.f ? s0 : 0.f;
        a_s[r * 512 + t + 256] = s1 > 0.f ? s1 : 0.f;
    }
    __syncthreads();

    // phase B: inter[r][m] = a[r] . W_g[m], W_g staged through smem in 8 chunks.
    // 384 outputs, 256 threads: thread t owns idx t, and idx t+256 iff t < 128.
    float accI0 = 0.f, accI1 = 0.f;
    int r0 = t / 48, m0 = t % 48;
    int r1 = (t + 256) / 48, m1 = (t + 256) % 48;   // only used when t < 128
    for (int c = 0; c < 8; c++) {
        __syncthreads();
#pragma unroll
        for (int i = 0; i < 3; i++) {
            int g4 = t + i * 256;                   // 768 float4 chunks of W_g slab
            int row = g4 >> 4, c4 = g4 & 15;
            float4 v = *(const float4*)(W_g + (size_t)row * 512 + c * 64 + c4 * 4);
            float* wp = wchunk + row * 65 + c4 * 4;
            wp[0] = v.x; wp[1] = v.y; wp[2] = v.z; wp[3] = v.w;
        }
        __syncthreads();
        if (t < 384) {
            const float* ar = a_s + r0 * 512 + c * 64;
            const float* wr = wchunk + m0 * 65;
            float s = 0.f;
#pragma unroll 8
            for (int kk = 0; kk < 64; kk++) s += ar[kk] * wr[kk];
            accI0 += s;
        }
        if (t < 128) {
            const float* ar = a_s + r1 * 512 + c * 64;
            const float* wr = wchunk + m1 * 65;
            float s = 0.f;
#pragma unroll 8
            for (int kk = 0; kk < 64; kk++) s += ar[kk] * wr[kk];
            accI1 += s;
        }
    }
    if (t < 384) g_inter[(size_t)cb * 384 + t] = accI0;
    if (t < 128) g_inter[(size_t)cb * 384 + t + 256] = accI1;
}

// ---------------- probe: keeps ncu capture window on main_kernel ------
__global__ void probe_kernel() {}

// ---------------- kernel 3: fused main, 1 bt/CTA, 256 thr, 2 CTAs/SM ---------
// smem (102912 B/CTA; x2 = 205824 <= 227KB):
//   Ah (half, 48 x 520)   @0       49920   (fp16 V, resident all of phase 1)
//   vs (half, 48 x 520)   @49920   49920
//   bvs (512 f32)         @99840    2048
//   inter(48) @101888 | wh(48) @102080 | zpart(96) @102272
//   red(2) @102656 | alpha(48) @102664 -> end 102856
#define OF_A     0
#define OF_VS    49920
#define OF_BVS   99840
#define OF_INTER 101888
#define OF_WH    102080
#define OF_ZP    102272
#define OF_RED   102656
#define OF_AL    102664
#define SMEM_BYTES 102912

__global__ __launch_bounds__(256, 2) void main_kernel(const float* __restrict__ video,
                                                      const float* __restrict__ b_video,
                                                      const float* __restrict__ W_h,
                                                      float* __restrict__ out) {
    extern __shared__ char smc[];
    uint32_t sbase = (uint32_t)__cvta_generic_to_shared(smc);
    __half* Ah     = (__half*)smc;
    __half* vs     = (__half*)(smc + OF_VS);
    float* bvs     = (float*)(smc + OF_BVS);
    float* inter_s = (float*)(smc + OF_INTER);
    float* wh_s    = (float*)(smc + OF_WH);
    float* zpart   = (float*)(smc + OF_ZP);
    float* red     = (float*)(smc + OF_RED);
    float* alpha_s = (float*)(smc + OF_AL);

    int t = threadIdx.x;
    int bt = blockIdx.x;
    int lane = t & 31, w = t >> 5;        // 8 warps
    int qid = lane >> 2, tq = lane & 3;

    const float* Vg = video + (size_t)bt * 48 * 512;

    // ---- phase 0: small vectors + full A load/convert (f32 -> fp16 smem) ----
    bvs[t] = b_video[t];
    bvs[t + 256] = b_video[t + 256];
    if (t < 48) { inter_s[t] = g_inter[(size_t)bt * 48 + t]; wh_s[t] = W_h[t]; }
#pragma unroll
    for (int i = 0; i < 24; i++) {
        int g = t + i * 256;              // 6144 float4 chunks (48 x 128)
        int row = g >> 7, c4 = g & 127;
        float4 v = *(const float4*)(Vg + (size_t)row * 512 + c4 * 4);
        *(uint2*)&Ah[row * SVH + c4 * 4] = make_uint2(packh2(v.x, v.y), packh2(v.z, v.w));
    }
    __syncthreads();

    // ---- phase 1: v = relu(V @ W_video^T + b)  (M=48, N=512, K=512) ----
    // Two N-passes; pass p: warp w owns h in [p*256 + w*32, +32): 4 n8 tiles.
    uint32_t lds_a = sbase + OF_A + (uint32_t)(((lane & 15) * SVH + (lane >> 4) * 8) * 2);

#pragma unroll 1
    for (int pass = 0; pass < 2; pass++) {
        float acc[3][4][4];
#pragma unroll
        for (int mt = 0; mt < 3; mt++)
#pragma unroll
            for (int j = 0; j < 4; j++)
#pragma unroll
                for (int r = 0; r < 4; r++) acc[mt][j][r] = 0.f;

        const uint2* Bp = g_Wvf + (size_t)((pass * 32 + w * 4)) * 32 * 32 + lane;
        uint2 bb[2][4];
#pragma unroll
        for (int j = 0; j < 4; j++) bb[0][j] = Bp[(size_t)(j * 32) * 32];

#pragma unroll 2
        for (int kg = 0; kg < 32; kg++) {
            int cur = kg & 1;
            if (kg < 31) {
#pragma unroll
                for (int j = 0; j < 4; j++)
                    bb[cur ^ 1][j] = Bp[(size_t)(j * 32 + kg + 1) * 32];
            }
            uint32_t a[3][4];
#pragma unroll
            for (int mt = 0; mt < 3; mt++)
                ldsm_x4(a[mt][0], a[mt][1], a[mt][2], a[mt][3],
                        lds_a + (uint32_t)((mt * 16 * SVH + kg * 16) * 2));
#pragma unroll
            for (int mt = 0; mt < 3; mt++)
#pragma unroll
                for (int j = 0; j < 4; j++)
                    mma_f16(acc[mt][j][0], acc[mt][j][1], acc[mt][j][2], acc[mt][j][3],
                            a[mt][0], a[mt][1], a[mt][2], a[mt][3],
                            bb[cur][j].x, bb[cur][j].y);
        }

        // epilogue for this pass: relu(+bias), pack fp16, store vs
#pragma unroll
        for (int mt = 0; mt < 3; mt++) {
#pragma unroll
            for (int j = 0; j < 4; j++) {
                int r0 = mt * 16 + qid;
                int h0 = pass * 256 + w * 32 + j * 8 + tq * 2;
                float bv0 = bvs[h0], bv1 = bvs[h0 + 1];
                float x0 = acc[mt][j][0] + bv0; x0 = x0 > 0.f ? x0 : 0.f;
                float x1 = acc[mt][j][1] + bv1; x1 = x1 > 0.f ? x1 : 0.f;
                float x2 = acc[mt][j][2] + bv0; x2 = x2 > 0.f ? x2 : 0.f;
                float x3 = acc[mt][j][3] + bv1; x3 = x3 > 0.f ? x3 : 0.f;
                *(uint32_t*)&vs[r0 * SVH + h0]       = packh2(x0, x1);
                *(uint32_t*)&vs[(r0 + 8) * SVH + h0] = packh2(x2, x3);
            }
        }
    }
    __syncthreads();

    // ---- phase 2: content = v @ W_v^T (+inter), tanh, z partials ----
    // 6 warps; warp owns m16 tile x 3 n8 tiles exclusively
    if (w < 6) {
        int mt = w >> 1, nh = w & 1;
        float cacc[3][4];
#pragma unroll
        for (int j = 0; j < 3; j++)
#pragma unroll
            for (int r = 0; r < 4; r++) cacc[j][r] = 0.f;

        const uint2* Bp2 = g_Wvvf + (size_t)(nh * 3) * 32 * 32 + lane;
        uint2 bb2[2][3];
#pragma unroll
        for (int j = 0; j < 3; j++) bb2[0][j] = Bp2[(size_t)(j * 32) * 32];

        uint32_t abase2 = sbase + OF_VS +
            (uint32_t)((((mt * 16 + (lane & 15)) * SVH) + (lane >> 4) * 8) * 2);
#pragma unroll 4
        for (int ks = 0; ks < 32; ks++) {
            int cur = ks & 1;
            if (ks < 31) {
#pragma unroll
                for (int j = 0; j < 3; j++)
                    bb2[cur ^ 1][j] = Bp2[(size_t)(j * 32 + ks + 1) * 32];
            }
            uint32_t a0, a1, a2, a3;
            ldsm_x4(a0, a1, a2, a3, abase2 + (uint32_t)(ks * 32));
#pragma unroll
            for (int j = 0; j < 3; j++)
                mma_f16(cacc[j][0], cacc[j][1], cacc[j][2], cacc[j][3],
                        a0, a1, a2, a3, bb2[cur][j].x, bb2[cur][j].y);
        }

        int n0 = mt * 16 + qid, n1 = n0 + 8;
        float i0 = inter_s[n0], i1 = inter_s[n1];
        float p0 = 0.f, p1 = 0.f;
#pragma unroll
        for (int j = 0; j < 3; j++) {
            int m0i = (nh * 3 + j) * 8 + tq * 2;
            float wh0 = wh_s[m0i], wh1 = wh_s[m0i + 1];
            p0 += tanhf(cacc[j][0] + i0) * wh0 + tanhf(cacc[j][1] + i0) * wh1;
            p1 += tanhf(cacc[j][2] + i1) * wh0 + tanhf(cacc[j][3] + i1) * wh1;
        }
        p0 += __shfl_xor_sync(0xffffffffu, p0, 1);
        p0 += __shfl_xor_sync(0xffffffffu, p0, 2);
        p1 += __shfl_xor_sync(0xffffffffu, p1, 1);
        p1 += __shfl_xor_sync(0xffffffffu, p1, 2);
        if (tq == 0) {
            zpart[n0 * 2 + nh] = p0;
            zpart[n1 * 2 + nh] = p1;
        }
    }
    __syncthreads();

    // ---- phase 3: softmax over 48 ----
    if (t < 48) alpha_s[t] = zpart[t * 2] + zpart[t * 2 + 1];
    __syncthreads();
    if (t == 0) {
        float m = -1e30f;
        for (int n = 0; n < 48; n++) m = fmaxf(m, alpha_s[n]);
        red[0] = m;
    }
    __syncthreads();
    if (t < 48) alpha_s[t] = expf(alpha_s[t] - red[0]);
    __syncthreads();
    if (t == 0) {
        float s = 0.f;
        for (int n = 0; n < 48; n++) s += alpha_s[n];
        red[1] = 1.0f / s;
    }
    __syncthreads();

    // ---- phase 4: c[k] = sum_n alpha[n] * V[n][k], exact V from global ----
    {
        float inv = red[1];
        float s0 = 0.f, s1 = 0.f;
#pragma unroll 8
        for (int n = 0; n < 48; n++) {
            float a = alpha_s[n];
            s0 += a * Vg[(size_t)n * 512 + t];
            s1 += a * Vg[(size_t)n * 512 + t + 256];
        }
        float* ob = out + (size_t)bt * 512;
        ob[t] = s0 * inv;
        ob[t + 256] = s1 * inv;
    }
}

// ---------------- launch ----------------
extern "C" void kernel_launch(void* const* d_in, const int* in_sizes, int n_in,
                              void* d_out, int out_size) {
    const float* audio   = (const float*)d_in[0];
    const float* video   = (const float*)d_in[1];
    const float* W_audio = (const float*)d_in[2];
    const float* b_audio = (const float*)d_in[3];
    const float* W_video = (const float*)d_in[4];
    const float* b_video = (const float*)d_in[5];
    const float* W_v     = (const float*)d_in[6];
    const float* W_g     = (const float*)d_in[7];
    const float* W_h     = (const float*)d_in[8];
    float* out = (float*)d_out;

    (void)in_sizes; (void)n_in; (void)out_size;

    cudaFuncSetAttribute(main_kernel, cudaFuncAttributeMaxDynamicSharedMemorySize, SMEM_BYTES);

    prep_kernel<<<536, 256>>>(W_video, W_v, W_audio);
    audio_kernel<<<BT_TOTAL / 8, 256>>>(audio, b_audio, W_g);
    probe_kernel<<<1, 32>>>();   // keeps ncu -s5 capture window on main_kernel
    main_kernel<<<BT_TOTAL, 256, SMEM_BYTES>>>(video, b_video, W_h, out);
}